// round 15
// baseline (speedup 1.0000x reference)
#include <cuda_runtime.h>
#include <cuda_fp16.h>
#include <cstdint>
#include <math.h>

#define B_  4
#define S_  2048
#define H_  16
#define DK_ 64
#define D_  1024

// Scratch (device globals — allocation-free rule)
__device__ float    g_v [B_*H_*S_*DK_];          // V fp32 [b,h,s,dk]
__device__ uint32_t g_qh[B_*H_*S_*32];           // fp16x2 pairs, hi only
__device__ uint32_t g_kh[B_*H_*S_*32];           // K hi
__device__ uint32_t g_kl[B_*H_*S_*32];           // K lo
__device__ uint32_t g_vh[B_*H_*DK_*(S_/2)];      // V hi, pairs along s
__device__ uint32_t g_vl[B_*H_*DK_*(S_/2)];      // V lo
__device__ uint32_t g_xh [B_*S_*512];            // x hi only
__device__ uint32_t g_wqh[3*D_*512];             // w_qkv hi
__device__ uint32_t g_wql[3*D_*512];             // w_qkv lo
__device__ uint32_t g_woh[D_*512];               // w_out hi
__device__ uint32_t g_wol[D_*512];               // w_out lo
__device__ uint32_t g_aoh[B_*S_*512];            // attention out, hi only

// ======================= helpers ===========================================
__device__ __forceinline__ void mma_f16(float* c,
                                        uint32_t a0, uint32_t a1, uint32_t a2, uint32_t a3,
                                        uint32_t b0, uint32_t b1) {
    asm volatile(
        "mma.sync.aligned.m16n8k16.row.col.f32.f16.f16.f32 "
        "{%0,%1,%2,%3}, {%4,%5,%6,%7}, {%8,%9}, {%0,%1,%2,%3};"
        : "+f"(c[0]), "+f"(c[1]), "+f"(c[2]), "+f"(c[3])
        : "r"(a0), "r"(a1), "r"(a2), "r"(a3), "r"(b0), "r"(b1));
}

__device__ __forceinline__ uint32_t pack_f16(float x, float y) {
    __half2 h = __floats2half2_rn(x, y);
    return *(uint32_t*)&h;
}
__device__ __forceinline__ void cvt_hilo_f16(float x, float y, uint32_t& hi, uint32_t& lo) {
    __half2 h = __floats2half2_rn(x, y);
    float hx = __half2float(__low2half(h));
    float hy = __half2float(__high2half(h));
    __half2 l = __floats2half2_rn(x - hx, y - hy);
    hi = *(uint32_t*)&h;
    lo = *(uint32_t*)&l;
}

__device__ __forceinline__ uint32_t smem_to_u32(const void* p) {
    uint32_t a;
    asm("{ .reg .u64 t; cvta.to.shared.u64 t, %1; cvt.u32.u64 %0, t; }"
        : "=r"(a) : "l"(p));
    return a;
}
__device__ __forceinline__ void cp_async16(uint32_t dst_smem, const void* src) {
    asm volatile("cp.async.cg.shared.global [%0], [%1], 16;"
                 :: "r"(dst_smem), "l"(src) : "memory");
}
__device__ __forceinline__ void cp_commit() {
    asm volatile("cp.async.commit_group;" ::: "memory");
}
template<int N>
__device__ __forceinline__ void cp_wait() {
    asm volatile("cp.async.wait_group %0;" :: "n"(N) : "memory");
}
__device__ __forceinline__ void ldsm_x4(uint32_t& r0, uint32_t& r1, uint32_t& r2,
                                        uint32_t& r3, uint32_t addr) {
    asm volatile("ldmatrix.sync.aligned.m8n8.x4.shared.b16 {%0,%1,%2,%3}, [%4];"
                 : "=r"(r0), "=r"(r1), "=r"(r2), "=r"(r3) : "r"(addr));
}
__device__ __forceinline__ float softcap(float s) {
    float e = __expf(s * 0.005f);
    return 50.f - __fdividef(100.f, e + 1.f);
}

// ---------------------------------------------------------------------------
// prep: fp32 -> fp16 pairs. P2: hi+lo (weights), P1: hi only (activations)
// ---------------------------------------------------------------------------
__global__ void prep_pack2(const float* __restrict__ src, uint32_t* __restrict__ dh,
                           uint32_t* __restrict__ dl, int npairs) {
    int i = blockIdx.x * blockDim.x + threadIdx.x;
    if (i >= npairs) return;
    float2 v = ((const float2*)src)[i];
    uint32_t hh, ll;
    cvt_hilo_f16(v.x, v.y, hh, ll);
    dh[i] = hh;
    dl[i] = ll;
}
__global__ void prep_pack1(const float* __restrict__ src, uint32_t* __restrict__ dh,
                           int npairs) {
    int i = blockIdx.x * blockDim.x + threadIdx.x;
    if (i >= npairs) return;
    float2 v = ((const float2*)src)[i];
    dh[i] = pack_f16(v.x, v.y);
}

// ---------------------------------------------------------------------------
// fp16x2 NT GEMM: C = A * (Wh + Wl)^T. BK=32. M-tile = MI*64 (MI=2 or 1).
// MI=2: warp tile 32x64 (4Mx2N); MI=1: warp tile 16x64.
// ---------------------------------------------------------------------------
#define PST 20

template<int MODE, int MI>
__global__ void __launch_bounds__(256, 2) mm_ldsm(const uint32_t* __restrict__ Ah_,
                                                  const uint32_t* __restrict__ Wh_,
                                                  const uint32_t* __restrict__ Wl_,
                                                  float* __restrict__ C) {
    constexpr int MROWS = MI * 64;
    constexpr int AW    = MROWS * PST;              // A words per buffer
    constexpr int BUFW  = AW + 2 * 128 * PST;       // total words per buffer

    extern __shared__ uint32_t smu[];
    const int tid = threadIdx.x;
    const int w = tid >> 5, l = tid & 31;
    const int wm = w & 3, wn = w >> 2;
    const int g = l >> 2, tq = l & 3;
    const int r8 = l & 7, seg = l >> 3;
    const int bm = blockIdx.y, bn = blockIdx.x;
    const uint32_t sb = smem_to_u32(smu);

    const uint32_t* Ag  = Ah_ + (size_t)bm * MROWS * 512;
    const uint32_t* Whg = Wh_ + (size_t)bn * 128 * 512;
    const uint32_t* Wlg = Wl_ + (size_t)bn * 128 * 512;

    const int crow = tid >> 1, cpp = (tid & 1) * 8;      // W copy map (128 rows)
    const int arow = (MI == 2) ? (tid >> 1) : (tid >> 2);
    const int apq  = (MI == 2) ? ((tid & 1) * 8) : ((tid & 3) * 4);

    auto issue = [&](int c, int p) {
        // A
        {
            uint32_t dst = sb + (uint32_t)((p * BUFW + arow * PST + apq) * 4);
            const uint32_t* s = Ag + (size_t)arow * 512 + c * 16 + apq;
            cp_async16(dst, s);
            if (MI == 2) cp_async16(dst + 16, s + 4);
        }
        // Wh, Wl
        {
            uint32_t dst = sb + (uint32_t)((p * BUFW + AW + crow * PST + cpp) * 4);
            const uint32_t* s = Whg + (size_t)crow * 512 + c * 16 + cpp;
            cp_async16(dst, s);
            cp_async16(dst + 16, s + 4);
            dst += 128 * PST * 4;
            s = Wlg + (size_t)crow * 512 + c * 16 + cpp;
            cp_async16(dst, s);
            cp_async16(dst + 16, s + 4);
        }
        cp_commit();
    };

    float acc[MI][8][4];
#pragma unroll
    for (int mi = 0; mi < MI; mi++)
#pragma unroll
        for (int ni = 0; ni < 8; ni++)
#pragma unroll
            for (int r = 0; r < 4; r++) acc[mi][ni][r] = 0.f;

    uint32_t aoff[MI], boff[4];
#pragma unroll
    for (int mi = 0; mi < MI; mi++)
        aoff[mi] = (uint32_t)((wm * (MI * 16) + mi * 16 + r8 + (seg & 1) * 8) * PST
                              + (seg >> 1) * 4);
#pragma unroll
    for (int nj = 0; nj < 4; nj++)
        boff[nj] = (uint32_t)(AW +
                              (wn * 64 + nj * 16 + r8 + (seg >> 1) * 8) * PST + (seg & 1) * 4);

    issue(0, 0);

    for (int c = 0; c < 32; c++) {
        const int p = c & 1;
        cp_wait<0>();
        __syncthreads();
        if (c + 1 < 32) issue(c + 1, p ^ 1);
        const uint32_t base = sb + (uint32_t)(p * BUFW * 4);

#pragma unroll
        for (int ks = 0; ks < 2; ks++) {
            const uint32_t kcb = ks * 8 * 4;
            uint32_t ah[MI][4];
#pragma unroll
            for (int mi = 0; mi < MI; mi++)
                ldsm_x4(ah[mi][0], ah[mi][1], ah[mi][2], ah[mi][3],
                        base + aoff[mi] * 4 + kcb);
#pragma unroll
            for (int njp = 0; njp < 2; njp++) {
                uint32_t bh[2][4], bl[2][4];
#pragma unroll
                for (int j2 = 0; j2 < 2; j2++) {
                    uint32_t bd = base + boff[njp * 2 + j2] * 4 + kcb;
                    ldsm_x4(bh[j2][0], bh[j2][1], bh[j2][2], bh[j2][3], bd);
                    ldsm_x4(bl[j2][0], bl[j2][1], bl[j2][2], bl[j2][3], bd + 128 * PST * 4);
                }
#pragma unroll
                for (int j2 = 0; j2 < 2; j2++)
#pragma unroll
                    for (int hf = 0; hf < 2; hf++)
#pragma unroll
                        for (int mi = 0; mi < MI; mi++)
                            mma_f16(acc[mi][(njp * 2 + j2) * 2 + hf],
                                    ah[mi][0], ah[mi][1], ah[mi][2], ah[mi][3],
                                    bh[j2][hf * 2], bh[j2][hf * 2 + 1]);
#pragma unroll
                for (int j2 = 0; j2 < 2; j2++)
#pragma unroll
                    for (int hf = 0; hf < 2; hf++)
#pragma unroll
                        for (int mi = 0; mi < MI; mi++)
                            mma_f16(acc[mi][(njp * 2 + j2) * 2 + hf],
                                    ah[mi][0], ah[mi][1], ah[mi][2], ah[mi][3],
                                    bl[j2][hf * 2], bl[j2][hf * 2 + 1]);
            }
        }
    }

    const int row0 = wm * (MI * 16), col0 = wn * 64;
#pragma unroll
    for (int mi = 0; mi < MI; mi++) {
#pragma unroll
        for (int half = 0; half < 2; half++) {
            int r = bm * MROWS + row0 + mi * 16 + g + half * 8;
#pragma unroll
            for (int ni = 0; ni < 8; ni++) {
                int cb = bn * 128 + col0 + ni * 8 + 2 * tq;
                float2 val = make_float2(acc[mi][ni][half * 2 + 0],
                                         acc[mi][ni][half * 2 + 1]);
                if (MODE == 0) {
                    int which = cb >> 10;          // 0:q 1:k 2:v
                    int h  = (cb >> 6) & 15;
                    int d0 = cb & 63;
                    int b  = r >> 11;
                    int s  = r & 2047;
                    if (which == 2) {
                        *(float2*)(g_v + (((size_t)(b * H_ + h) * S_ + s) * DK_ + d0)) = val;
                    } else {
                        int pr = d0 >> 1;
                        float invf = exp2f(-(float)pr * (13.28771237954945f / 32.0f));
                        float ang = (float)s * invf;
                        float sn, cs;
                        sincosf(ang, &sn, &cs);
                        float ev = val.x * cs - val.y * sn;
                        float od = val.x * sn + val.y * cs;
                        size_t idx = ((size_t)(b * H_ + h) * S_ + s) * 32 + pr;
                        if (which == 0) {
                            g_qh[idx] = pack_f16(ev, od);          // Q hi only
                        } else {
                            uint32_t hh, ll;
                            cvt_hilo_f16(ev, od, hh, ll);          // K hi+lo
                            g_kh[idx] = hh; g_kl[idx] = ll;
                        }
                    }
                } else {
                    *(float2*)(C + (size_t)r * D_ + cb) = val;
                }
            }
        }
    }
}

#define MM0_SMEM_BYTES (2 * (2*64*PST + 2*128*PST) * 4)   // 61440 (MI=2)
#define MM1_SMEM_BYTES (2 * (1*64*PST + 2*128*PST) * 4)   // 51200 (MI=1)

// ---------------------------------------------------------------------------
// V transpose + hi/lo fp16 split: g_v [b,h,s,dk] -> g_vh/g_vl [b,h][dk][s/2]
// ---------------------------------------------------------------------------
__global__ void __launch_bounds__(256) v_convert() {
    __shared__ float ts[64 * 65];
    const int tid = threadIdx.x;
    const int kt = blockIdx.x, h = blockIdx.y, b = blockIdx.z;
    const int bh = b * H_ + h;

    const float* src = g_v + ((size_t)bh * S_ + kt * 64) * DK_;
#pragma unroll
    for (int i = 0; i < 4; i++) {
        int f = tid + i * 256;
        int row = f >> 4, c4 = (f & 15) * 4;
        float4 v = *(const float4*)(src + row * DK_ + c4);
        ts[row * 65 + c4 + 0] = v.x;
        ts[row * 65 + c4 + 1] = v.y;
        ts[row * 65 + c4 + 2] = v.z;
        ts[row * 65 + c4 + 3] = v.w;
    }
    __syncthreads();

    const int w = tid >> 5, p = tid & 31;
#pragma unroll
    for (int i = 0; i < 8; i++) {
        int c = w * 8 + i;
        float x1 = ts[(2 * p) * 65 + c];
        float x2 = ts[(2 * p + 1) * 65 + c];
        uint32_t hh, ll;
        cvt_hilo_f16(x1, x2, hh, ll);
        size_t o = ((size_t)bh * 64 + c) * (S_ / 2) + kt * 32 + p;
        g_vh[o] = hh;
        g_vl[o] = ll;
    }
}

// ---------------------------------------------------------------------------
// Flash attention: BQ=128, fp16x2 (Q/P hi-only, K/V hi+lo), cp.async dbl-buf,
// ldmatrix fragments (round-12 configuration, no diag group skip).
// ---------------------------------------------------------------------------
#define FST 36
#define FQW  (128 * FST)              // Q hi only
#define FKVW (4 * 64 * FST)
#define FLASH_SMEM_BYTES ((FQW + 2 * FKVW) * 4)   // 92160

__global__ void __launch_bounds__(256, 2) flash_mma() {
    extern __shared__ uint32_t su[];
    uint32_t* Qh = su;

    const int tid = threadIdx.x;
    const int w = tid >> 5, l = tid & 31;
    const int g = l >> 2, tq = l & 3;
    const int r8 = l & 7, seg = l >> 3;
    const int q0 = (int)(gridDim.x - 1 - blockIdx.x) * 128;
    const int h = blockIdx.y, b = blockIdx.z;
    const size_t bhp = (size_t)(b * H_ + h) * S_ * 32;
    const size_t bhv = (size_t)(b * H_ + h) * 64;
    const uint32_t sb = smem_to_u32(su);

    const int kvrow = tid >> 2;
    const int kvq   = (tid & 3) * 8;

    auto issue_kv = [&](int kt, int s) {
        uint32_t base = sb + (uint32_t)((FQW + s * FKVW + kvrow * FST + kvq) * 4);
        const uint32_t* k_h = g_kh + bhp + (size_t)(kt * 64 + kvrow) * 32 + kvq;
        const uint32_t* k_l = g_kl + bhp + (size_t)(kt * 64 + kvrow) * 32 + kvq;
        const uint32_t* v_h = g_vh + (bhv + kvrow) * (S_ / 2) + kt * 32 + kvq;
        const uint32_t* v_l = g_vl + (bhv + kvrow) * (S_ / 2) + kt * 32 + kvq;
        cp_async16(base,                      k_h);
        cp_async16(base + 16,                 k_h + 4);
        cp_async16(base + 64*FST*4,           k_l);
        cp_async16(base + 64*FST*4 + 16,      k_l + 4);
        cp_async16(base + 2*64*FST*4,         v_h);
        cp_async16(base + 2*64*FST*4 + 16,    v_h + 4);
        cp_async16(base + 3*64*FST*4,         v_l);
        cp_async16(base + 3*64*FST*4 + 16,    v_l + 4);
        cp_commit();
    };

    issue_kv(0, 0);
    {
        int row = tid >> 1, pb = (tid & 1) * 16;
        const uint32_t* sh = g_qh + bhp + (size_t)(q0 + row) * 32 + pb;
        uint32_t d = sb + (uint32_t)((row * FST + pb) * 4);
#pragma unroll
        for (int j = 0; j < 4; j++)
            cp_async16(d + j * 16, sh + j * 4);
        cp_commit();
    }
    cp_wait<0>();
    __syncthreads();

    uint32_t qh[4][4];
#pragma unroll
    for (int kk = 0; kk < 4; kk++) {
        int ra = (w * 16 + g) * FST + kk * 8 + tq;
        int rb = ra + 8 * FST;
        qh[kk][0] = Qh[ra];     qh[kk][1] = Qh[rb];
        qh[kk][2] = Qh[ra + 4]; qh[kk][3] = Qh[rb + 4];
    }

    uint32_t fboff[4];
#pragma unroll
    for (int nj = 0; nj < 4; nj++)
        fboff[nj] = (uint32_t)((nj * 16 + r8 + (seg >> 1) * 8) * FST + (seg & 1) * 4);

    float m0 = -INFINITY, m1 = -INFINITY, l0s = 0.f, l1s = 0.f;
    float o[8][4];
#pragma unroll
    for (int ni = 0; ni < 8; ni++)
#pragma unroll
        for (int r = 0; r < 4; r++) o[ni][r] = 0.f;

    const int ig0 = q0 + w * 16 + g;
    const int ig1 = ig0 + 8;
    const int rowmax = q0 + w * 16 + 15;
    const int nkt = (q0 + 127) >> 6;

    for (int kt = 0; kt <= nkt; kt++) {
        const int p = kt & 1;
        if (kt > 0) cp_wait<0>();
        __syncthreads();
        if (kt < nkt) issue_kv(kt + 1, p ^ 1);

        if (kt * 64 <= rowmax) {
            const uint32_t kbase = sb + (uint32_t)((FQW + p * FKVW) * 4);
            const uint32_t vbase = kbase + 2 * 64 * FST * 4;

            // S = Q K^T (2-pass fp16)
            float sc[8][4];
#pragma unroll
            for (int ni = 0; ni < 8; ni++)
#pragma unroll
                for (int r = 0; r < 4; r++) sc[ni][r] = 0.f;
#pragma unroll
            for (int kk = 0; kk < 4; kk++) {
                const uint32_t kcb = kk * 8 * 4;
#pragma unroll
                for (int nig = 0; nig < 2; nig++) {
                    uint32_t bh[2][4], bl[2][4];
#pragma unroll
                    for (int j2 = 0; j2 < 2; j2++) {
                        uint32_t ad = kbase + fboff[nig * 2 + j2] * 4 + kcb;
                        ldsm_x4(bh[j2][0], bh[j2][1], bh[j2][2], bh[j2][3], ad);
                        ldsm_x4(bl[j2][0], bl[j2][1], bl[j2][2], bl[j2][3], ad + 64 * FST * 4);
                    }
#pragma unroll
                    for (int j2 = 0; j2 < 2; j2++)
#pragma unroll
                        for (int hf = 0; hf < 2; hf++)
                            mma_f16(sc[nig * 4 + j2 * 2 + hf],
                                    qh[kk][0], qh[kk][1], qh[kk][2], qh[kk][3],
                                    bh[j2][hf * 2], bh[j2][hf * 2 + 1]);
#pragma unroll
                    for (int j2 = 0; j2 < 2; j2++)
#pragma unroll
                        for (int hf = 0; hf < 2; hf++)
                            mma_f16(sc[nig * 4 + j2 * 2 + hf],
                                    qh[kk][0], qh[kk][1], qh[kk][2], qh[kk][3],
                                    bl[j2][hf * 2], bl[j2][hf * 2 + 1]);
                }
            }

            // scale + softcap (fast) + causal mask
            const bool diag = (kt * 64 + 63) > ig0;
#pragma unroll
            for (int ni = 0; ni < 8; ni++) {
                int jg = kt * 64 + ni * 8 + 2 * tq;
#pragma unroll
                for (int r = 0; r < 4; r++) {
                    float v = softcap(sc[ni][r]);
                    if (diag) {
                        int col = jg + (r & 1);
                        int row = (r < 2) ? ig0 : ig1;
                        if (col > row) v = -1e30f;
                    }
                    sc[ni][r] = v;
                }
            }

            // online softmax
            float mx0 = -INFINITY, mx1 = -INFINITY;
#pragma unroll
            for (int ni = 0; ni < 8; ni++) {
                mx0 = fmaxf(mx0, fmaxf(sc[ni][0], sc[ni][1]));
                mx1 = fmaxf(mx1, fmaxf(sc[ni][2], sc[ni][3]));
            }
            mx0 = fmaxf(mx0, __shfl_xor_sync(0xffffffffu, mx0, 1));
            mx0 = fmaxf(mx0, __shfl_xor_sync(0xffffffffu, mx0, 2));
            mx1 = fmaxf(mx1, __shfl_xor_sync(0xffffffffu, mx1, 1));
            mx1 = fmaxf(mx1, __shfl_xor_sync(0xffffffffu, mx1, 2));
            float mn0 = fmaxf(m0, mx0), mn1 = fmaxf(m1, mx1);
            float s0 = 0.f, s1 = 0.f;
#pragma unroll
            for (int ni = 0; ni < 8; ni++) {
                sc[ni][0] = __expf(sc[ni][0] - mn0);
                sc[ni][1] = __expf(sc[ni][1] - mn0);
                sc[ni][2] = __expf(sc[ni][2] - mn1);
                sc[ni][3] = __expf(sc[ni][3] - mn1);
                s0 += sc[ni][0] + sc[ni][1];
                s1 += sc[ni][2] + sc[ni][3];
            }
            s0 += __shfl_xor_sync(0xffffffffu, s0, 1);
            s0 += __shfl_xor_sync(0xffffffffu, s0, 2);
            s1 += __shfl_xor_sync(0xffffffffu, s1, 1);
            s1 += __shfl_xor_sync(0xffffffffu, s1, 2);
            float c0 = __expf(m0 - mn0), c1 = __expf(m1 - mn1);
            l0s = l0s * c0 + s0; l1s = l1s * c1 + s1;
            m0 = mn0; m1 = mn1;
#pragma unroll
            for (int ni = 0; ni < 8; ni++) {
                o[ni][0] *= c0; o[ni][1] *= c0;
                o[ni][2] *= c1; o[ni][3] *= c1;
            }

            // pack P hi-only A-fragments
            uint32_t ph[4][4];
#pragma unroll
            for (int kk = 0; kk < 4; kk++) {
                int n0 = 2 * kk, n1 = 2 * kk + 1;
                ph[kk][0] = pack_f16(sc[n0][0], sc[n0][1]);
                ph[kk][1] = pack_f16(sc[n0][2], sc[n0][3]);
                ph[kk][2] = pack_f16(sc[n1][0], sc[n1][1]);
                ph[kk][3] = pack_f16(sc[n1][2], sc[n1][3]);
            }

            // O += P V (2-pass fp16)
#pragma unroll
            for (int kk = 0; kk < 4; kk++) {
                const uint32_t kcb = kk * 8 * 4;
#pragma unroll
                for (int nig = 0; nig < 2; nig++) {
                    uint32_t bh[2][4], bl[2][4];
#pragma unroll
                    for (int j2 = 0; j2 < 2; j2++) {
                        uint32_t ad = vbase + fboff[nig * 2 + j2] * 4 + kcb;
                        ldsm_x4(bh[j2][0], bh[j2][1], bh[j2][2], bh[j2][3], ad);
                        ldsm_x4(bl[j2][0], bl[j2][1], bl[j2][2], bl[j2][3], ad + 64 * FST * 4);
                    }
#pragma unroll
                    for (int j2 = 0; j2 < 2; j2++)
#pragma unroll
                        for (int hf = 0; hf < 2; hf++)
                            mma_f16(o[nig * 4 + j2 * 2 + hf],
                                    ph[kk][0], ph[kk][1], ph[kk][2], ph[kk][3],
                                    bh[j2][hf * 2], bh[j2][hf * 2 + 1]);
#pragma unroll
                    for (int j2 = 0; j2 < 2; j2++)
#pragma unroll
                        for (int hf = 0; hf < 2; hf++)
                            mma_f16(o[nig * 4 + j2 * 2 + hf],
                                    ph[kk][0], ph[kk][1], ph[kk][2], ph[kk][3],
                                    bl[j2][hf * 2], bl[j2][hf * 2 + 1]);
                }
            }
        }
    }

    // epilogue: normalize, write hi-only packed pairs [b,s][512]
    float inv0 = 1.0f / l0s, inv1 = 1.0f / l1s;
    size_t r0b = (size_t)(b * S_ + ig0) * 512 + h * 32;
    size_t r1b = (size_t)(b * S_ + ig1) * 512 + h * 32;
#pragma unroll
    for (int ni = 0; ni < 8; ni++) {
        int pr = ni * 4 + tq;
        g_aoh[r0b + pr] = pack_f16(o[ni][0] * inv0, o[ni][1] * inv0);
        g_aoh[r1b + pr] = pack_f16(o[ni][2] * inv1, o[ni][3] * inv1);
    }
}

// ---------------------------------------------------------------------------
extern "C" void kernel_launch(void* const* d_in, const int* in_sizes, int n_in,
                              void* d_out, int out_size) {
    const float* x     = (const float*)d_in[0];
    const float* w_qkv = (const float*)d_in[1];
    const float* w_out = (const float*)d_in[2];
    float* out = (float*)d_out;

    cudaFuncSetAttribute((const void*)mm_ldsm<0,2>,
                         cudaFuncAttributeMaxDynamicSharedMemorySize, MM0_SMEM_BYTES);
    cudaFuncSetAttribute((const void*)mm_ldsm<1,1>,
                         cudaFuncAttributeMaxDynamicSharedMemorySize, MM1_SMEM_BYTES);
    cudaFuncSetAttribute(flash_mma, cudaFuncAttributeMaxDynamicSharedMemorySize,
                         FLASH_SMEM_BYTES);

    uint32_t *xh, *wqh, *wql, *woh, *wol, *aoh;
    cudaGetSymbolAddress((void**)&xh,  g_xh);
    cudaGetSymbolAddress((void**)&wqh, g_wqh); cudaGetSymbolAddress((void**)&wql, g_wql);
    cudaGetSymbolAddress((void**)&woh, g_woh); cudaGetSymbolAddress((void**)&wol, g_wol);
    cudaGetSymbolAddress((void**)&aoh, g_aoh);

    // 0) pre-pack: activations hi-only, weights hi+lo
    prep_pack1<<<(B_*S_*512 + 255) / 256, 256>>>(x,     xh,  B_*S_*512);
    prep_pack2<<<(3*D_*512  + 255) / 256, 256>>>(w_qkv, wqh, wql, 3*D_*512);
    prep_pack2<<<(D_*512    + 255) / 256, 256>>>(w_out, woh, wol, D_*512);

    // 1) QKV projection + fused RoPE (M-tile 128)
    mm_ldsm<0,2><<<dim3(24, 64), 256, MM0_SMEM_BYTES>>>(xh, wqh, wql, nullptr);

    // 2) V transpose + hi/lo split
    v_convert<<<dim3(S_/64, H_, B_), 256>>>();

    // 3) Flash attention
    flash_mma<<<dim3(S_/128, H_, B_), 256, FLASH_SMEM_BYTES>>>();

    // 4) Output projection (M-tile 64 -> 1024 CTAs, balanced waves)
    mm_ldsm<1,1><<<dim3(8, 128), 256, MM1_SMEM_BYTES>>>(aoh, woh, wol, out);
}

// round 16
// speedup vs baseline: 1.0360x; 1.0360x over previous
#include <cuda_runtime.h>
#include <cuda_fp16.h>
#include <cstdint>
#include <math.h>

#define B_  4
#define S_  2048
#define H_  16
#define DK_ 64
#define D_  1024

// Scratch (device globals — allocation-free rule)
__device__ float    g_v [B_*H_*S_*DK_];          // V fp32 [b,h,s,dk]
__device__ uint32_t g_qh[B_*H_*S_*32];           // fp16x2 pairs, hi only
__device__ uint32_t g_kh[B_*H_*S_*32];           // K hi
__device__ uint32_t g_kl[B_*H_*S_*32];           // K lo
__device__ uint32_t g_vh[B_*H_*DK_*(S_/2)];      // V hi, pairs along s
__device__ uint32_t g_vl[B_*H_*DK_*(S_/2)];      // V lo
__device__ uint32_t g_xh [B_*S_*512];            // x hi only
__device__ uint32_t g_wqh[3*D_*512];             // w_qkv hi
__device__ uint32_t g_wql[3*D_*512];             // w_qkv lo
__device__ uint32_t g_woh[D_*512];               // w_out hi
__device__ uint32_t g_wol[D_*512];               // w_out lo
__device__ uint32_t g_aoh[B_*S_*512];            // attention out, hi only

// ======================= helpers ===========================================
__device__ __forceinline__ void mma_f16(float* c,
                                        uint32_t a0, uint32_t a1, uint32_t a2, uint32_t a3,
                                        uint32_t b0, uint32_t b1) {
    asm volatile(
        "mma.sync.aligned.m16n8k16.row.col.f32.f16.f16.f32 "
        "{%0,%1,%2,%3}, {%4,%5,%6,%7}, {%8,%9}, {%0,%1,%2,%3};"
        : "+f"(c[0]), "+f"(c[1]), "+f"(c[2]), "+f"(c[3])
        : "r"(a0), "r"(a1), "r"(a2), "r"(a3), "r"(b0), "r"(b1));
}

__device__ __forceinline__ uint32_t pack_f16(float x, float y) {
    __half2 h = __floats2half2_rn(x, y);
    return *(uint32_t*)&h;
}
__device__ __forceinline__ void cvt_hilo_f16(float x, float y, uint32_t& hi, uint32_t& lo) {
    __half2 h = __floats2half2_rn(x, y);
    float hx = __half2float(__low2half(h));
    float hy = __half2float(__high2half(h));
    __half2 l = __floats2half2_rn(x - hx, y - hy);
    hi = *(uint32_t*)&h;
    lo = *(uint32_t*)&l;
}

__device__ __forceinline__ uint32_t smem_to_u32(const void* p) {
    uint32_t a;
    asm("{ .reg .u64 t; cvta.to.shared.u64 t, %1; cvt.u32.u64 %0, t; }"
        : "=r"(a) : "l"(p));
    return a;
}
__device__ __forceinline__ void cp_async16(uint32_t dst_smem, const void* src) {
    asm volatile("cp.async.cg.shared.global [%0], [%1], 16;"
                 :: "r"(dst_smem), "l"(src) : "memory");
}
__device__ __forceinline__ void cp_commit() {
    asm volatile("cp.async.commit_group;" ::: "memory");
}
template<int N>
__device__ __forceinline__ void cp_wait() {
    asm volatile("cp.async.wait_group %0;" :: "n"(N) : "memory");
}
__device__ __forceinline__ void ldsm_x4(uint32_t& r0, uint32_t& r1, uint32_t& r2,
                                        uint32_t& r3, uint32_t addr) {
    asm volatile("ldmatrix.sync.aligned.m8n8.x4.shared.b16 {%0,%1,%2,%3}, [%4];"
                 : "=r"(r0), "=r"(r1), "=r"(r2), "=r"(r3) : "r"(addr));
}
__device__ __forceinline__ float softcap(float s) {
    float e = __expf(s * 0.005f);
    return 50.f - __fdividef(100.f, e + 1.f);
}

// ---------------------------------------------------------------------------
// fused prep: one launch packs x (hi only), w_qkv (hi+lo), w_out (hi+lo)
// ---------------------------------------------------------------------------
#define NPX  (B_*S_*512)        // 4194304 pairs
#define NPWQ (3*D_*512)         // 1572864
#define NPWO (D_*512)           // 524288

__global__ void prep_all(const float* __restrict__ x,
                         const float* __restrict__ wq,
                         const float* __restrict__ wo) {
    int i = blockIdx.x * blockDim.x + threadIdx.x;
    if (i < NPX) {
        float2 v = ((const float2*)x)[i];
        g_xh[i] = pack_f16(v.x, v.y);
    } else if (i < NPX + NPWQ) {
        int j = i - NPX;
        float2 v = ((const float2*)wq)[j];
        uint32_t hh, ll;
        cvt_hilo_f16(v.x, v.y, hh, ll);
        g_wqh[j] = hh; g_wql[j] = ll;
    } else if (i < NPX + NPWQ + NPWO) {
        int j = i - NPX - NPWQ;
        float2 v = ((const float2*)wo)[j];
        uint32_t hh, ll;
        cvt_hilo_f16(v.x, v.y, hh, ll);
        g_woh[j] = hh; g_wol[j] = ll;
    }
}

// ---------------------------------------------------------------------------
// fp16x2 NT GEMM: C = A * (Wh + Wl)^T. BK=32 (16 pairs per chunk, 32 chunks).
// CTA 128x128, 256 thr (8 warps 4Mx2N). Round-12 configuration.
// ---------------------------------------------------------------------------
#define PST 20
#define MMBUF (3 * 128 * PST)
#define MM_SMEM_BYTES (2 * MMBUF * 4)      // 61440

template<int MODE>
__global__ void __launch_bounds__(256, 2) mm_ldsm(const uint32_t* __restrict__ Ah_,
                                                  const uint32_t* __restrict__ Wh_,
                                                  const uint32_t* __restrict__ Wl_,
                                                  float* __restrict__ C) {
    extern __shared__ uint32_t smu[];
    const int tid = threadIdx.x;
    const int w = tid >> 5, l = tid & 31;
    const int wm = w & 3, wn = w >> 2;
    const int g = l >> 2, tq = l & 3;
    const int r8 = l & 7, seg = l >> 3;
    const int bm = blockIdx.y, bn = blockIdx.x;
    const uint32_t sb = smem_to_u32(smu);

    const uint32_t* srcs[3] = {
        Ah_ + (size_t)bm * 128 * 512,
        Wh_ + (size_t)bn * 128 * 512,
        Wl_ + (size_t)bn * 128 * 512 };

    const int crow = tid >> 1, cpp = (tid & 1) * 8;

    auto issue = [&](int c, int p) {
        uint32_t dst = sb + (uint32_t)((p * MMBUF + crow * PST + cpp) * 4);
#pragma unroll
        for (int m = 0; m < 3; m++) {
            const uint32_t* s = srcs[m] + (size_t)crow * 512 + c * 16 + cpp;
            cp_async16(dst + m * 128 * PST * 4, s);
            cp_async16(dst + m * 128 * PST * 4 + 16, s + 4);
        }
        cp_commit();
    };

    float acc[2][8][4];
#pragma unroll
    for (int mi = 0; mi < 2; mi++)
#pragma unroll
        for (int ni = 0; ni < 8; ni++)
#pragma unroll
            for (int r = 0; r < 4; r++) acc[mi][ni][r] = 0.f;

    uint32_t aoff[2], boff[4];
#pragma unroll
    for (int mi = 0; mi < 2; mi++)
        aoff[mi] = (uint32_t)((wm * 32 + mi * 16 + r8 + (seg & 1) * 8) * PST + (seg >> 1) * 4);
#pragma unroll
    for (int nj = 0; nj < 4; nj++)
        boff[nj] = (uint32_t)(128 * PST +
                              (wn * 64 + nj * 16 + r8 + (seg >> 1) * 8) * PST + (seg & 1) * 4);

    issue(0, 0);

    for (int c = 0; c < 32; c++) {
        const int p = c & 1;
        cp_wait<0>();
        __syncthreads();
        if (c + 1 < 32) issue(c + 1, p ^ 1);
        const uint32_t base = sb + (uint32_t)(p * MMBUF * 4);

#pragma unroll
        for (int ks = 0; ks < 2; ks++) {
            const uint32_t kcb = ks * 8 * 4;
            uint32_t ah[2][4];
#pragma unroll
            for (int mi = 0; mi < 2; mi++)
                ldsm_x4(ah[mi][0], ah[mi][1], ah[mi][2], ah[mi][3],
                        base + aoff[mi] * 4 + kcb);
#pragma unroll
            for (int njp = 0; njp < 2; njp++) {
                uint32_t bh[2][4], bl[2][4];
#pragma unroll
                for (int j2 = 0; j2 < 2; j2++) {
                    uint32_t bd = base + boff[njp * 2 + j2] * 4 + kcb;
                    ldsm_x4(bh[j2][0], bh[j2][1], bh[j2][2], bh[j2][3], bd);
                    ldsm_x4(bl[j2][0], bl[j2][1], bl[j2][2], bl[j2][3], bd + 128 * PST * 4);
                }
#pragma unroll
                for (int j2 = 0; j2 < 2; j2++)
#pragma unroll
                    for (int hf = 0; hf < 2; hf++)
#pragma unroll
                        for (int mi = 0; mi < 2; mi++)
                            mma_f16(acc[mi][(njp * 2 + j2) * 2 + hf],
                                    ah[mi][0], ah[mi][1], ah[mi][2], ah[mi][3],
                                    bh[j2][hf * 2], bh[j2][hf * 2 + 1]);
#pragma unroll
                for (int j2 = 0; j2 < 2; j2++)
#pragma unroll
                    for (int hf = 0; hf < 2; hf++)
#pragma unroll
                        for (int mi = 0; mi < 2; mi++)
                            mma_f16(acc[mi][(njp * 2 + j2) * 2 + hf],
                                    ah[mi][0], ah[mi][1], ah[mi][2], ah[mi][3],
                                    bl[j2][hf * 2], bl[j2][hf * 2 + 1]);
            }
        }
    }

    const int row0 = wm * 32, col0 = wn * 64;
#pragma unroll
    for (int mi = 0; mi < 2; mi++) {
#pragma unroll
        for (int half = 0; half < 2; half++) {
            int r = bm * 128 + row0 + mi * 16 + g + half * 8;
#pragma unroll
            for (int ni = 0; ni < 8; ni++) {
                int cb = bn * 128 + col0 + ni * 8 + 2 * tq;
                float2 val = make_float2(acc[mi][ni][half * 2 + 0],
                                         acc[mi][ni][half * 2 + 1]);
                if (MODE == 0) {
                    int which = cb >> 10;          // 0:q 1:k 2:v
                    int h  = (cb >> 6) & 15;
                    int d0 = cb & 63;
                    int b  = r >> 11;
                    int s  = r & 2047;
                    if (which == 2) {
                        *(float2*)(g_v + (((size_t)(b * H_ + h) * S_ + s) * DK_ + d0)) = val;
                    } else {
                        int pr = d0 >> 1;
                        float invf = exp2f(-(float)pr * (13.28771237954945f / 32.0f));
                        float ang = (float)s * invf;
                        float sn, cs;
                        sincosf(ang, &sn, &cs);
                        float ev = val.x * cs - val.y * sn;
                        float od = val.x * sn + val.y * cs;
                        size_t idx = ((size_t)(b * H_ + h) * S_ + s) * 32 + pr;
                        if (which == 0) {
                            g_qh[idx] = pack_f16(ev, od);          // Q hi only
                        } else {
                            uint32_t hh, ll;
                            cvt_hilo_f16(ev, od, hh, ll);          // K hi+lo
                            g_kh[idx] = hh; g_kl[idx] = ll;
                        }
                    }
                } else {
                    *(float2*)(C + (size_t)r * D_ + cb) = val;
                }
            }
        }
    }
}

// ---------------------------------------------------------------------------
// V transpose + hi/lo fp16 split: 2 tiles per 128-thread block (grid halved)
// ---------------------------------------------------------------------------
__global__ void __launch_bounds__(128) v_convert() {
    __shared__ float ts[64 * 65];
    const int tid = threadIdx.x;
    const int h = blockIdx.y, b = blockIdx.z;
    const int bh = b * H_ + h;

#pragma unroll
    for (int half = 0; half < 2; half++) {
        const int kt = blockIdx.x * 2 + half;
        if (half) __syncthreads();           // protect ts reuse
        const float* src = g_v + ((size_t)bh * S_ + kt * 64) * DK_;
#pragma unroll
        for (int i = 0; i < 8; i++) {
            int f = tid + i * 128;
            int row = f >> 4, c4 = (f & 15) * 4;
            float4 v = *(const float4*)(src + row * DK_ + c4);
            ts[row * 65 + c4 + 0] = v.x;
            ts[row * 65 + c4 + 1] = v.y;
            ts[row * 65 + c4 + 2] = v.z;
            ts[row * 65 + c4 + 3] = v.w;
        }
        __syncthreads();

        const int w = tid >> 5, p = tid & 31;
#pragma unroll
        for (int i = 0; i < 16; i++) {
            int c = w * 16 + i;
            float x1 = ts[(2 * p) * 65 + c];
            float x2 = ts[(2 * p + 1) * 65 + c];
            uint32_t hh, ll;
            cvt_hilo_f16(x1, x2, hh, ll);
            size_t o = ((size_t)bh * 64 + c) * (S_ / 2) + kt * 32 + p;
            g_vh[o] = hh;
            g_vl[o] = ll;
        }
    }
}

// ---------------------------------------------------------------------------
// Flash attention: BQ=128, fp16x2 (Q/P hi-only, K/V hi+lo), cp.async dbl-buf,
// ldmatrix fragments (round-12 configuration).
// ---------------------------------------------------------------------------
#define FST 36
#define FQW  (128 * FST)              // Q hi only
#define FKVW (4 * 64 * FST)
#define FLASH_SMEM_BYTES ((FQW + 2 * FKVW) * 4)   // 92160

__global__ void __launch_bounds__(256, 2) flash_mma() {
    extern __shared__ uint32_t su[];
    uint32_t* Qh = su;

    const int tid = threadIdx.x;
    const int w = tid >> 5, l = tid & 31;
    const int g = l >> 2, tq = l & 3;
    const int r8 = l & 7, seg = l >> 3;
    const int q0 = (int)(gridDim.x - 1 - blockIdx.x) * 128;
    const int h = blockIdx.y, b = blockIdx.z;
    const size_t bhp = (size_t)(b * H_ + h) * S_ * 32;
    const size_t bhv = (size_t)(b * H_ + h) * 64;
    const uint32_t sb = smem_to_u32(su);

    const int kvrow = tid >> 2;
    const int kvq   = (tid & 3) * 8;

    auto issue_kv = [&](int kt, int s) {
        uint32_t base = sb + (uint32_t)((FQW + s * FKVW + kvrow * FST + kvq) * 4);
        const uint32_t* k_h = g_kh + bhp + (size_t)(kt * 64 + kvrow) * 32 + kvq;
        const uint32_t* k_l = g_kl + bhp + (size_t)(kt * 64 + kvrow) * 32 + kvq;
        const uint32_t* v_h = g_vh + (bhv + kvrow) * (S_ / 2) + kt * 32 + kvq;
        const uint32_t* v_l = g_vl + (bhv + kvrow) * (S_ / 2) + kt * 32 + kvq;
        cp_async16(base,                      k_h);
        cp_async16(base + 16,                 k_h + 4);
        cp_async16(base + 64*FST*4,           k_l);
        cp_async16(base + 64*FST*4 + 16,      k_l + 4);
        cp_async16(base + 2*64*FST*4,         v_h);
        cp_async16(base + 2*64*FST*4 + 16,    v_h + 4);
        cp_async16(base + 3*64*FST*4,         v_l);
        cp_async16(base + 3*64*FST*4 + 16,    v_l + 4);
        cp_commit();
    };

    issue_kv(0, 0);
    {
        int row = tid >> 1, pb = (tid & 1) * 16;
        const uint32_t* sh = g_qh + bhp + (size_t)(q0 + row) * 32 + pb;
        uint32_t d = sb + (uint32_t)((row * FST + pb) * 4);
#pragma unroll
        for (int j = 0; j < 4; j++)
            cp_async16(d + j * 16, sh + j * 4);
        cp_commit();
    }
    cp_wait<0>();
    __syncthreads();

    uint32_t qh[4][4];
#pragma unroll
    for (int kk = 0; kk < 4; kk++) {
        int ra = (w * 16 + g) * FST + kk * 8 + tq;
        int rb = ra + 8 * FST;
        qh[kk][0] = Qh[ra];     qh[kk][1] = Qh[rb];
        qh[kk][2] = Qh[ra + 4]; qh[kk][3] = Qh[rb + 4];
    }

    uint32_t fboff[4];
#pragma unroll
    for (int nj = 0; nj < 4; nj++)
        fboff[nj] = (uint32_t)((nj * 16 + r8 + (seg >> 1) * 8) * FST + (seg & 1) * 4);

    float m0 = -INFINITY, m1 = -INFINITY, l0s = 0.f, l1s = 0.f;
    float o[8][4];
#pragma unroll
    for (int ni = 0; ni < 8; ni++)
#pragma unroll
        for (int r = 0; r < 4; r++) o[ni][r] = 0.f;

    const int ig0 = q0 + w * 16 + g;
    const int ig1 = ig0 + 8;
    const int rowmax = q0 + w * 16 + 15;
    const int nkt = (q0 + 127) >> 6;

    for (int kt = 0; kt <= nkt; kt++) {
        const int p = kt & 1;
        if (kt > 0) cp_wait<0>();
        __syncthreads();
        if (kt < nkt) issue_kv(kt + 1, p ^ 1);

        if (kt * 64 <= rowmax) {
            const uint32_t kbase = sb + (uint32_t)((FQW + p * FKVW) * 4);
            const uint32_t vbase = kbase + 2 * 64 * FST * 4;

            float sc[8][4];
#pragma unroll
            for (int ni = 0; ni < 8; ni++)
#pragma unroll
                for (int r = 0; r < 4; r++) sc[ni][r] = 0.f;
#pragma unroll
            for (int kk = 0; kk < 4; kk++) {
                const uint32_t kcb = kk * 8 * 4;
#pragma unroll
                for (int nig = 0; nig < 2; nig++) {
                    uint32_t bh[2][4], bl[2][4];
#pragma unroll
                    for (int j2 = 0; j2 < 2; j2++) {
                        uint32_t ad = kbase + fboff[nig * 2 + j2] * 4 + kcb;
                        ldsm_x4(bh[j2][0], bh[j2][1], bh[j2][2], bh[j2][3], ad);
                        ldsm_x4(bl[j2][0], bl[j2][1], bl[j2][2], bl[j2][3], ad + 64 * FST * 4);
                    }
#pragma unroll
                    for (int j2 = 0; j2 < 2; j2++)
#pragma unroll
                        for (int hf = 0; hf < 2; hf++)
                            mma_f16(sc[nig * 4 + j2 * 2 + hf],
                                    qh[kk][0], qh[kk][1], qh[kk][2], qh[kk][3],
                                    bh[j2][hf * 2], bh[j2][hf * 2 + 1]);
#pragma unroll
                    for (int j2 = 0; j2 < 2; j2++)
#pragma unroll
                        for (int hf = 0; hf < 2; hf++)
                            mma_f16(sc[nig * 4 + j2 * 2 + hf],
                                    qh[kk][0], qh[kk][1], qh[kk][2], qh[kk][3],
                                    bl[j2][hf * 2], bl[j2][hf * 2 + 1]);
                }
            }

            const bool diag = (kt * 64 + 63) > ig0;
#pragma unroll
            for (int ni = 0; ni < 8; ni++) {
                int jg = kt * 64 + ni * 8 + 2 * tq;
#pragma unroll
                for (int r = 0; r < 4; r++) {
                    float v = softcap(sc[ni][r]);
                    if (diag) {
                        int col = jg + (r & 1);
                        int row = (r < 2) ? ig0 : ig1;
                        if (col > row) v = -1e30f;
                    }
                    sc[ni][r] = v;
                }
            }

            float mx0 = -INFINITY, mx1 = -INFINITY;
#pragma unroll
            for (int ni = 0; ni < 8; ni++) {
                mx0 = fmaxf(mx0, fmaxf(sc[ni][0], sc[ni][1]));
                mx1 = fmaxf(mx1, fmaxf(sc[ni][2], sc[ni][3]));
            }
            mx0 = fmaxf(mx0, __shfl_xor_sync(0xffffffffu, mx0, 1));
            mx0 = fmaxf(mx0, __shfl_xor_sync(0xffffffffu, mx0, 2));
            mx1 = fmaxf(mx1, __shfl_xor_sync(0xffffffffu, mx1, 1));
            mx1 = fmaxf(mx1, __shfl_xor_sync(0xffffffffu, mx1, 2));
            float mn0 = fmaxf(m0, mx0), mn1 = fmaxf(m1, mx1);
            float s0 = 0.f, s1 = 0.f;
#pragma unroll
            for (int ni = 0; ni < 8; ni++) {
                sc[ni][0] = __expf(sc[ni][0] - mn0);
                sc[ni][1] = __expf(sc[ni][1] - mn0);
                sc[ni][2] = __expf(sc[ni][2] - mn1);
                sc[ni][3] = __expf(sc[ni][3] - mn1);
                s0 += sc[ni][0] + sc[ni][1];
                s1 += sc[ni][2] + sc[ni][3];
            }
            s0 += __shfl_xor_sync(0xffffffffu, s0, 1);
            s0 += __shfl_xor_sync(0xffffffffu, s0, 2);
            s1 += __shfl_xor_sync(0xffffffffu, s1, 1);
            s1 += __shfl_xor_sync(0xffffffffu, s1, 2);
            float c0 = __expf(m0 - mn0), c1 = __expf(m1 - mn1);
            l0s = l0s * c0 + s0; l1s = l1s * c1 + s1;
            m0 = mn0; m1 = mn1;
#pragma unroll
            for (int ni = 0; ni < 8; ni++) {
                o[ni][0] *= c0; o[ni][1] *= c0;
                o[ni][2] *= c1; o[ni][3] *= c1;
            }

            uint32_t ph[4][4];
#pragma unroll
            for (int kk = 0; kk < 4; kk++) {
                int n0 = 2 * kk, n1 = 2 * kk + 1;
                ph[kk][0] = pack_f16(sc[n0][0], sc[n0][1]);
                ph[kk][1] = pack_f16(sc[n0][2], sc[n0][3]);
                ph[kk][2] = pack_f16(sc[n1][0], sc[n1][1]);
                ph[kk][3] = pack_f16(sc[n1][2], sc[n1][3]);
            }

#pragma unroll
            for (int kk = 0; kk < 4; kk++) {
                const uint32_t kcb = kk * 8 * 4;
#pragma unroll
                for (int nig = 0; nig < 2; nig++) {
                    uint32_t bh[2][4], bl[2][4];
#pragma unroll
                    for (int j2 = 0; j2 < 2; j2++) {
                        uint32_t ad = vbase + fboff[nig * 2 + j2] * 4 + kcb;
                        ldsm_x4(bh[j2][0], bh[j2][1], bh[j2][2], bh[j2][3], ad);
                        ldsm_x4(bl[j2][0], bl[j2][1], bl[j2][2], bl[j2][3], ad + 64 * FST * 4);
                    }
#pragma unroll
                    for (int j2 = 0; j2 < 2; j2++)
#pragma unroll
                        for (int hf = 0; hf < 2; hf++)
                            mma_f16(o[nig * 4 + j2 * 2 + hf],
                                    ph[kk][0], ph[kk][1], ph[kk][2], ph[kk][3],
                                    bh[j2][hf * 2], bh[j2][hf * 2 + 1]);
#pragma unroll
                    for (int j2 = 0; j2 < 2; j2++)
#pragma unroll
                        for (int hf = 0; hf < 2; hf++)
                            mma_f16(o[nig * 4 + j2 * 2 + hf],
                                    ph[kk][0], ph[kk][1], ph[kk][2], ph[kk][3],
                                    bl[j2][hf * 2], bl[j2][hf * 2 + 1]);
                }
            }
        }
    }

    float inv0 = 1.0f / l0s, inv1 = 1.0f / l1s;
    size_t r0b = (size_t)(b * S_ + ig0) * 512 + h * 32;
    size_t r1b = (size_t)(b * S_ + ig1) * 512 + h * 32;
#pragma unroll
    for (int ni = 0; ni < 8; ni++) {
        int pr = ni * 4 + tq;
        g_aoh[r0b + pr] = pack_f16(o[ni][0] * inv0, o[ni][1] * inv0);
        g_aoh[r1b + pr] = pack_f16(o[ni][2] * inv1, o[ni][3] * inv1);
    }
}

// ---------------------------------------------------------------------------
extern "C" void kernel_launch(void* const* d_in, const int* in_sizes, int n_in,
                              void* d_out, int out_size) {
    const float* x     = (const float*)d_in[0];
    const float* w_qkv = (const float*)d_in[1];
    const float* w_out = (const float*)d_in[2];
    float* out = (float*)d_out;

    cudaFuncSetAttribute(mm_ldsm<0>, cudaFuncAttributeMaxDynamicSharedMemorySize, MM_SMEM_BYTES);
    cudaFuncSetAttribute(mm_ldsm<1>, cudaFuncAttributeMaxDynamicSharedMemorySize, MM_SMEM_BYTES);
    cudaFuncSetAttribute(flash_mma,  cudaFuncAttributeMaxDynamicSharedMemorySize, FLASH_SMEM_BYTES);

    uint32_t *xh, *wqh, *wql, *woh, *wol, *aoh;
    cudaGetSymbolAddress((void**)&xh,  g_xh);
    cudaGetSymbolAddress((void**)&wqh, g_wqh); cudaGetSymbolAddress((void**)&wql, g_wql);
    cudaGetSymbolAddress((void**)&woh, g_woh); cudaGetSymbolAddress((void**)&wol, g_wol);
    cudaGetSymbolAddress((void**)&aoh, g_aoh);

    // 0) fused pre-pack (single launch)
    prep_all<<<(NPX + NPWQ + NPWO + 255) / 256, 256>>>(x, w_qkv, w_out);

    // 1) QKV projection + fused RoPE
    mm_ldsm<0><<<dim3(24, 64), 256, MM_SMEM_BYTES>>>(xh, wqh, wql, nullptr);

    // 2) V transpose + hi/lo split (2 tiles per block)
    v_convert<<<dim3(S_/128, H_, B_), 128>>>();

    // 3) Flash attention
    flash_mma<<<dim3(S_/128, H_, B_), 256, FLASH_SMEM_BYTES>>>();

    // 4) Output projection
    mm_ldsm<1><<<dim3(8, 64), 256, MM_SMEM_BYTES>>>(aoh, woh, wol, out);
}

// round 17
// speedup vs baseline: 1.0972x; 1.0591x over previous
#include <cuda_runtime.h>
#include <cuda_fp16.h>
#include <cstdint>
#include <math.h>

#define B_  4
#define S_  2048
#define H_  16
#define DK_ 64
#define D_  1024

// Scratch (device globals — allocation-free rule)
__device__ float    g_v [B_*H_*S_*DK_];          // V fp32 [b,h,s,dk]
__device__ uint32_t g_qh[B_*H_*S_*32];           // fp16x2 pairs, hi only
__device__ uint32_t g_kh[B_*H_*S_*32];           // K hi
__device__ uint32_t g_kl[B_*H_*S_*32];           // K lo
__device__ uint32_t g_vh[B_*H_*DK_*(S_/2)];      // V hi, pairs along s
__device__ uint32_t g_xh [B_*S_*512];            // x hi only
__device__ uint32_t g_wqh[3*D_*512];             // w_qkv hi
__device__ uint32_t g_wql[3*D_*512];             // w_qkv lo
__device__ uint32_t g_woh[D_*512];               // w_out hi
__device__ uint32_t g_wol[D_*512];               // w_out lo
__device__ uint32_t g_aoh[B_*S_*512];            // attention out, hi only

// ======================= helpers ===========================================
__device__ __forceinline__ void mma_f16(float* c,
                                        uint32_t a0, uint32_t a1, uint32_t a2, uint32_t a3,
                                        uint32_t b0, uint32_t b1) {
    asm volatile(
        "mma.sync.aligned.m16n8k16.row.col.f32.f16.f16.f32 "
        "{%0,%1,%2,%3}, {%4,%5,%6,%7}, {%8,%9}, {%0,%1,%2,%3};"
        : "+f"(c[0]), "+f"(c[1]), "+f"(c[2]), "+f"(c[3])
        : "r"(a0), "r"(a1), "r"(a2), "r"(a3), "r"(b0), "r"(b1));
}

__device__ __forceinline__ uint32_t pack_f16(float x, float y) {
    __half2 h = __floats2half2_rn(x, y);
    return *(uint32_t*)&h;
}
__device__ __forceinline__ void cvt_hilo_f16(float x, float y, uint32_t& hi, uint32_t& lo) {
    __half2 h = __floats2half2_rn(x, y);
    float hx = __half2float(__low2half(h));
    float hy = __half2float(__high2half(h));
    __half2 l = __floats2half2_rn(x - hx, y - hy);
    hi = *(uint32_t*)&h;
    lo = *(uint32_t*)&l;
}

__device__ __forceinline__ uint32_t smem_to_u32(const void* p) {
    uint32_t a;
    asm("{ .reg .u64 t; cvta.to.shared.u64 t, %1; cvt.u32.u64 %0, t; }"
        : "=r"(a) : "l"(p));
    return a;
}
__device__ __forceinline__ void cp_async16(uint32_t dst_smem, const void* src) {
    asm volatile("cp.async.cg.shared.global [%0], [%1], 16;"
                 :: "r"(dst_smem), "l"(src) : "memory");
}
__device__ __forceinline__ void cp_commit() {
    asm volatile("cp.async.commit_group;" ::: "memory");
}
template<int N>
__device__ __forceinline__ void cp_wait() {
    asm volatile("cp.async.wait_group %0;" :: "n"(N) : "memory");
}
__device__ __forceinline__ void ldsm_x4(uint32_t& r0, uint32_t& r1, uint32_t& r2,
                                        uint32_t& r3, uint32_t addr) {
    asm volatile("ldmatrix.sync.aligned.m8n8.x4.shared.b16 {%0,%1,%2,%3}, [%4];"
                 : "=r"(r0), "=r"(r1), "=r"(r2), "=r"(r3) : "r"(addr));
}
__device__ __forceinline__ float softcap(float s) {
    float e = __expf(s * 0.005f);
    return 50.f - __fdividef(100.f, e + 1.f);
}

// ---------------------------------------------------------------------------
// fused prep: one launch packs x (hi only), w_qkv (hi+lo), w_out (hi+lo)
// ---------------------------------------------------------------------------
#define NPX  (B_*S_*512)
#define NPWQ (3*D_*512)
#define NPWO (D_*512)

__global__ void prep_all(const float* __restrict__ x,
                         const float* __restrict__ wq,
                         const float* __restrict__ wo) {
    int i = blockIdx.x * blockDim.x + threadIdx.x;
    if (i < NPX) {
        float2 v = ((const float2*)x)[i];
        g_xh[i] = pack_f16(v.x, v.y);
    } else if (i < NPX + NPWQ) {
        int j = i - NPX;
        float2 v = ((const float2*)wq)[j];
        uint32_t hh, ll;
        cvt_hilo_f16(v.x, v.y, hh, ll);
        g_wqh[j] = hh; g_wql[j] = ll;
    } else if (i < NPX + NPWQ + NPWO) {
        int j = i - NPX - NPWQ;
        float2 v = ((const float2*)wo)[j];
        uint32_t hh, ll;
        cvt_hilo_f16(v.x, v.y, hh, ll);
        g_woh[j] = hh; g_wol[j] = ll;
    }
}

// ---------------------------------------------------------------------------
// fp16x2 NT GEMM: C = A * (Wh + Wl)^T. BK=32 (16 pairs per chunk, 32 chunks).
// CTA 128x128, 256 thr (8 warps 4Mx2N). Round-12 configuration.
// ---------------------------------------------------------------------------
#define PST 20
#define MMBUF (3 * 128 * PST)
#define MM_SMEM_BYTES (2 * MMBUF * 4)      // 61440

template<int MODE>
__global__ void __launch_bounds__(256, 2) mm_ldsm(const uint32_t* __restrict__ Ah_,
                                                  const uint32_t* __restrict__ Wh_,
                                                  const uint32_t* __restrict__ Wl_,
                                                  float* __restrict__ C) {
    extern __shared__ uint32_t smu[];
    const int tid = threadIdx.x;
    const int w = tid >> 5, l = tid & 31;
    const int wm = w & 3, wn = w >> 2;
    const int g = l >> 2, tq = l & 3;
    const int r8 = l & 7, seg = l >> 3;
    const int bm = blockIdx.y, bn = blockIdx.x;
    const uint32_t sb = smem_to_u32(smu);

    const uint32_t* srcs[3] = {
        Ah_ + (size_t)bm * 128 * 512,
        Wh_ + (size_t)bn * 128 * 512,
        Wl_ + (size_t)bn * 128 * 512 };

    const int crow = tid >> 1, cpp = (tid & 1) * 8;

    auto issue = [&](int c, int p) {
        uint32_t dst = sb + (uint32_t)((p * MMBUF + crow * PST + cpp) * 4);
#pragma unroll
        for (int m = 0; m < 3; m++) {
            const uint32_t* s = srcs[m] + (size_t)crow * 512 + c * 16 + cpp;
            cp_async16(dst + m * 128 * PST * 4, s);
            cp_async16(dst + m * 128 * PST * 4 + 16, s + 4);
        }
        cp_commit();
    };

    float acc[2][8][4];
#pragma unroll
    for (int mi = 0; mi < 2; mi++)
#pragma unroll
        for (int ni = 0; ni < 8; ni++)
#pragma unroll
            for (int r = 0; r < 4; r++) acc[mi][ni][r] = 0.f;

    uint32_t aoff[2], boff[4];
#pragma unroll
    for (int mi = 0; mi < 2; mi++)
        aoff[mi] = (uint32_t)((wm * 32 + mi * 16 + r8 + (seg & 1) * 8) * PST + (seg >> 1) * 4);
#pragma unroll
    for (int nj = 0; nj < 4; nj++)
        boff[nj] = (uint32_t)(128 * PST +
                              (wn * 64 + nj * 16 + r8 + (seg >> 1) * 8) * PST + (seg & 1) * 4);

    issue(0, 0);

    for (int c = 0; c < 32; c++) {
        const int p = c & 1;
        cp_wait<0>();
        __syncthreads();
        if (c + 1 < 32) issue(c + 1, p ^ 1);
        const uint32_t base = sb + (uint32_t)(p * MMBUF * 4);

#pragma unroll
        for (int ks = 0; ks < 2; ks++) {
            const uint32_t kcb = ks * 8 * 4;
            uint32_t ah[2][4];
#pragma unroll
            for (int mi = 0; mi < 2; mi++)
                ldsm_x4(ah[mi][0], ah[mi][1], ah[mi][2], ah[mi][3],
                        base + aoff[mi] * 4 + kcb);
#pragma unroll
            for (int njp = 0; njp < 2; njp++) {
                uint32_t bh[2][4], bl[2][4];
#pragma unroll
                for (int j2 = 0; j2 < 2; j2++) {
                    uint32_t bd = base + boff[njp * 2 + j2] * 4 + kcb;
                    ldsm_x4(bh[j2][0], bh[j2][1], bh[j2][2], bh[j2][3], bd);
                    ldsm_x4(bl[j2][0], bl[j2][1], bl[j2][2], bl[j2][3], bd + 128 * PST * 4);
                }
#pragma unroll
                for (int j2 = 0; j2 < 2; j2++)
#pragma unroll
                    for (int hf = 0; hf < 2; hf++)
#pragma unroll
                        for (int mi = 0; mi < 2; mi++)
                            mma_f16(acc[mi][(njp * 2 + j2) * 2 + hf],
                                    ah[mi][0], ah[mi][1], ah[mi][2], ah[mi][3],
                                    bh[j2][hf * 2], bh[j2][hf * 2 + 1]);
#pragma unroll
                for (int j2 = 0; j2 < 2; j2++)
#pragma unroll
                    for (int hf = 0; hf < 2; hf++)
#pragma unroll
                        for (int mi = 0; mi < 2; mi++)
                            mma_f16(acc[mi][(njp * 2 + j2) * 2 + hf],
                                    ah[mi][0], ah[mi][1], ah[mi][2], ah[mi][3],
                                    bl[j2][hf * 2], bl[j2][hf * 2 + 1]);
            }
        }
    }

    const int row0 = wm * 32, col0 = wn * 64;
#pragma unroll
    for (int mi = 0; mi < 2; mi++) {
#pragma unroll
        for (int half = 0; half < 2; half++) {
            int r = bm * 128 + row0 + mi * 16 + g + half * 8;
#pragma unroll
            for (int ni = 0; ni < 8; ni++) {
                int cb = bn * 128 + col0 + ni * 8 + 2 * tq;
                float2 val = make_float2(acc[mi][ni][half * 2 + 0],
                                         acc[mi][ni][half * 2 + 1]);
                if (MODE == 0) {
                    int which = cb >> 10;          // 0:q 1:k 2:v
                    int h  = (cb >> 6) & 15;
                    int d0 = cb & 63;
                    int b  = r >> 11;
                    int s  = r & 2047;
                    if (which == 2) {
                        *(float2*)(g_v + (((size_t)(b * H_ + h) * S_ + s) * DK_ + d0)) = val;
                    } else {
                        int pr = d0 >> 1;
                        float invf = exp2f(-(float)pr * (13.28771237954945f / 32.0f));
                        float ang = (float)s * invf;
                        float sn, cs;
                        sincosf(ang, &sn, &cs);
                        float ev = val.x * cs - val.y * sn;
                        float od = val.x * sn + val.y * cs;
                        size_t idx = ((size_t)(b * H_ + h) * S_ + s) * 32 + pr;
                        if (which == 0) {
                            g_qh[idx] = pack_f16(ev, od);          // Q hi only
                        } else {
                            uint32_t hh, ll;
                            cvt_hilo_f16(ev, od, hh, ll);          // K hi+lo
                            g_kh[idx] = hh; g_kl[idx] = ll;
                        }
                    }
                } else {
                    *(float2*)(C + (size_t)r * D_ + cb) = val;
                }
            }
        }
    }
}

// ---------------------------------------------------------------------------
// V transpose + fp16 pack (hi only): 2 tiles per 128-thread block
// ---------------------------------------------------------------------------
__global__ void __launch_bounds__(128) v_convert() {
    __shared__ float ts[64 * 65];
    const int tid = threadIdx.x;
    const int h = blockIdx.y, b = blockIdx.z;
    const int bh = b * H_ + h;

#pragma unroll
    for (int half = 0; half < 2; half++) {
        const int kt = blockIdx.x * 2 + half;
        if (half) __syncthreads();           // protect ts reuse
        const float* src = g_v + ((size_t)bh * S_ + kt * 64) * DK_;
#pragma unroll
        for (int i = 0; i < 8; i++) {
            int f = tid + i * 128;
            int row = f >> 4, c4 = (f & 15) * 4;
            float4 v = *(const float4*)(src + row * DK_ + c4);
            ts[row * 65 + c4 + 0] = v.x;
            ts[row * 65 + c4 + 1] = v.y;
            ts[row * 65 + c4 + 2] = v.z;
            ts[row * 65 + c4 + 3] = v.w;
        }
        __syncthreads();

        const int w = tid >> 5, p = tid & 31;
#pragma unroll
        for (int i = 0; i < 16; i++) {
            int c = w * 16 + i;
            float x1 = ts[(2 * p) * 65 + c];
            float x2 = ts[(2 * p + 1) * 65 + c];
            size_t o = ((size_t)bh * 64 + c) * (S_ / 2) + kt * 32 + p;
            g_vh[o] = pack_f16(x1, x2);
        }
    }
}

// ---------------------------------------------------------------------------
// Flash attention: BQ=128, fp16x2 (Q/P/V hi-only, K hi+lo), cp.async dbl-buf,
// ldmatrix fragments. PV single-pass (V-lo correction dropped).
// ---------------------------------------------------------------------------
#define FST 36
#define FQW  (128 * FST)              // Q hi only
#define FKVW (3 * 64 * FST)           // Kh | Kl | Vh per stage
#define FLASH_SMEM_BYTES ((FQW + 2 * FKVW) * 4)   // 73728

__global__ void __launch_bounds__(256, 2) flash_mma() {
    extern __shared__ uint32_t su[];
    uint32_t* Qh = su;

    const int tid = threadIdx.x;
    const int w = tid >> 5, l = tid & 31;
    const int g = l >> 2, tq = l & 3;
    const int r8 = l & 7, seg = l >> 3;
    const int q0 = (int)(gridDim.x - 1 - blockIdx.x) * 128;
    const int h = blockIdx.y, b = blockIdx.z;
    const size_t bhp = (size_t)(b * H_ + h) * S_ * 32;
    const size_t bhv = (size_t)(b * H_ + h) * 64;
    const uint32_t sb = smem_to_u32(su);

    const int kvrow = tid >> 2;
    const int kvq   = (tid & 3) * 8;

    auto issue_kv = [&](int kt, int s) {
        uint32_t base = sb + (uint32_t)((FQW + s * FKVW + kvrow * FST + kvq) * 4);
        const uint32_t* k_h = g_kh + bhp + (size_t)(kt * 64 + kvrow) * 32 + kvq;
        const uint32_t* k_l = g_kl + bhp + (size_t)(kt * 64 + kvrow) * 32 + kvq;
        const uint32_t* v_h = g_vh + (bhv + kvrow) * (S_ / 2) + kt * 32 + kvq;
        cp_async16(base,                      k_h);
        cp_async16(base + 16,                 k_h + 4);
        cp_async16(base + 64*FST*4,           k_l);
        cp_async16(base + 64*FST*4 + 16,      k_l + 4);
        cp_async16(base + 2*64*FST*4,         v_h);
        cp_async16(base + 2*64*FST*4 + 16,    v_h + 4);
        cp_commit();
    };

    issue_kv(0, 0);
    {
        int row = tid >> 1, pb = (tid & 1) * 16;
        const uint32_t* sh = g_qh + bhp + (size_t)(q0 + row) * 32 + pb;
        uint32_t d = sb + (uint32_t)((row * FST + pb) * 4);
#pragma unroll
        for (int j = 0; j < 4; j++)
            cp_async16(d + j * 16, sh + j * 4);
        cp_commit();
    }
    cp_wait<0>();
    __syncthreads();

    uint32_t qh[4][4];
#pragma unroll
    for (int kk = 0; kk < 4; kk++) {
        int ra = (w * 16 + g) * FST + kk * 8 + tq;
        int rb = ra + 8 * FST;
        qh[kk][0] = Qh[ra];     qh[kk][1] = Qh[rb];
        qh[kk][2] = Qh[ra + 4]; qh[kk][3] = Qh[rb + 4];
    }

    uint32_t fboff[4];
#pragma unroll
    for (int nj = 0; nj < 4; nj++)
        fboff[nj] = (uint32_t)((nj * 16 + r8 + (seg >> 1) * 8) * FST + (seg & 1) * 4);

    float m0 = -INFINITY, m1 = -INFINITY, l0s = 0.f, l1s = 0.f;
    float o[8][4];
#pragma unroll
    for (int ni = 0; ni < 8; ni++)
#pragma unroll
        for (int r = 0; r < 4; r++) o[ni][r] = 0.f;

    const int ig0 = q0 + w * 16 + g;
    const int ig1 = ig0 + 8;
    const int rowmax = q0 + w * 16 + 15;
    const int nkt = (q0 + 127) >> 6;

    for (int kt = 0; kt <= nkt; kt++) {
        const int p = kt & 1;
        if (kt > 0) cp_wait<0>();
        __syncthreads();
        if (kt < nkt) issue_kv(kt + 1, p ^ 1);

        if (kt * 64 <= rowmax) {
            const uint32_t kbase = sb + (uint32_t)((FQW + p * FKVW) * 4);
            const uint32_t vbase = kbase + 2 * 64 * FST * 4;

            // S = Q K^T (2-pass: K hi + K lo)
            float sc[8][4];
#pragma unroll
            for (int ni = 0; ni < 8; ni++)
#pragma unroll
                for (int r = 0; r < 4; r++) sc[ni][r] = 0.f;
#pragma unroll
            for (int kk = 0; kk < 4; kk++) {
                const uint32_t kcb = kk * 8 * 4;
#pragma unroll
                for (int nig = 0; nig < 2; nig++) {
                    uint32_t bh[2][4], bl[2][4];
#pragma unroll
                    for (int j2 = 0; j2 < 2; j2++) {
                        uint32_t ad = kbase + fboff[nig * 2 + j2] * 4 + kcb;
                        ldsm_x4(bh[j2][0], bh[j2][1], bh[j2][2], bh[j2][3], ad);
                        ldsm_x4(bl[j2][0], bl[j2][1], bl[j2][2], bl[j2][3], ad + 64 * FST * 4);
                    }
#pragma unroll
                    for (int j2 = 0; j2 < 2; j2++)
#pragma unroll
                        for (int hf = 0; hf < 2; hf++)
                            mma_f16(sc[nig * 4 + j2 * 2 + hf],
                                    qh[kk][0], qh[kk][1], qh[kk][2], qh[kk][3],
                                    bh[j2][hf * 2], bh[j2][hf * 2 + 1]);
#pragma unroll
                    for (int j2 = 0; j2 < 2; j2++)
#pragma unroll
                        for (int hf = 0; hf < 2; hf++)
                            mma_f16(sc[nig * 4 + j2 * 2 + hf],
                                    qh[kk][0], qh[kk][1], qh[kk][2], qh[kk][3],
                                    bl[j2][hf * 2], bl[j2][hf * 2 + 1]);
                }
            }

            // scale + softcap (fast) + causal mask
            const bool diag = (kt * 64 + 63) > ig0;
#pragma unroll
            for (int ni = 0; ni < 8; ni++) {
                int jg = kt * 64 + ni * 8 + 2 * tq;
#pragma unroll
                for (int r = 0; r < 4; r++) {
                    float v = softcap(sc[ni][r]);
                    if (diag) {
                        int col = jg + (r & 1);
                        int row = (r < 2) ? ig0 : ig1;
                        if (col > row) v = -1e30f;
                    }
                    sc[ni][r] = v;
                }
            }

            // online softmax
            float mx0 = -INFINITY, mx1 = -INFINITY;
#pragma unroll
            for (int ni = 0; ni < 8; ni++) {
                mx0 = fmaxf(mx0, fmaxf(sc[ni][0], sc[ni][1]));
                mx1 = fmaxf(mx1, fmaxf(sc[ni][2], sc[ni][3]));
            }
            mx0 = fmaxf(mx0, __shfl_xor_sync(0xffffffffu, mx0, 1));
            mx0 = fmaxf(mx0, __shfl_xor_sync(0xffffffffu, mx0, 2));
            mx1 = fmaxf(mx1, __shfl_xor_sync(0xffffffffu, mx1, 1));
            mx1 = fmaxf(mx1, __shfl_xor_sync(0xffffffffu, mx1, 2));
            float mn0 = fmaxf(m0, mx0), mn1 = fmaxf(m1, mx1);
            float s0 = 0.f, s1 = 0.f;
#pragma unroll
            for (int ni = 0; ni < 8; ni++) {
                sc[ni][0] = __expf(sc[ni][0] - mn0);
                sc[ni][1] = __expf(sc[ni][1] - mn0);
                sc[ni][2] = __expf(sc[ni][2] - mn1);
                sc[ni][3] = __expf(sc[ni][3] - mn1);
                s0 += sc[ni][0] + sc[ni][1];
                s1 += sc[ni][2] + sc[ni][3];
            }
            s0 += __shfl_xor_sync(0xffffffffu, s0, 1);
            s0 += __shfl_xor_sync(0xffffffffu, s0, 2);
            s1 += __shfl_xor_sync(0xffffffffu, s1, 1);
            s1 += __shfl_xor_sync(0xffffffffu, s1, 2);
            float c0 = __expf(m0 - mn0), c1 = __expf(m1 - mn1);
            l0s = l0s * c0 + s0; l1s = l1s * c1 + s1;
            m0 = mn0; m1 = mn1;
#pragma unroll
            for (int ni = 0; ni < 8; ni++) {
                o[ni][0] *= c0; o[ni][1] *= c0;
                o[ni][2] *= c1; o[ni][3] *= c1;
            }

            // pack P hi-only A-fragments
            uint32_t ph[4][4];
#pragma unroll
            for (int kk = 0; kk < 4; kk++) {
                int n0 = 2 * kk, n1 = 2 * kk + 1;
                ph[kk][0] = pack_f16(sc[n0][0], sc[n0][1]);
                ph[kk][1] = pack_f16(sc[n0][2], sc[n0][3]);
                ph[kk][2] = pack_f16(sc[n1][0], sc[n1][1]);
                ph[kk][3] = pack_f16(sc[n1][2], sc[n1][3]);
            }

            // O += P V (single pass, V hi only)
#pragma unroll
            for (int kk = 0; kk < 4; kk++) {
                const uint32_t kcb = kk * 8 * 4;
#pragma unroll
                for (int nig = 0; nig < 2; nig++) {
                    uint32_t bh[2][4];
#pragma unroll
                    for (int j2 = 0; j2 < 2; j2++) {
                        uint32_t ad = vbase + fboff[nig * 2 + j2] * 4 + kcb;
                        ldsm_x4(bh[j2][0], bh[j2][1], bh[j2][2], bh[j2][3], ad);
                    }
#pragma unroll
                    for (int j2 = 0; j2 < 2; j2++)
#pragma unroll
                        for (int hf = 0; hf < 2; hf++)
                            mma_f16(o[nig * 4 + j2 * 2 + hf],
                                    ph[kk][0], ph[kk][1], ph[kk][2], ph[kk][3],
                                    bh[j2][hf * 2], bh[j2][hf * 2 + 1]);
                }
            }
        }
    }

    // epilogue: normalize, write hi-only packed pairs [b,s][512]
    float inv0 = 1.0f / l0s, inv1 = 1.0f / l1s;
    size_t r0b = (size_t)(b * S_ + ig0) * 512 + h * 32;
    size_t r1b = (size_t)(b * S_ + ig1) * 512 + h * 32;
#pragma unroll
    for (int ni = 0; ni < 8; ni++) {
        int pr = ni * 4 + tq;
        g_aoh[r0b + pr] = pack_f16(o[ni][0] * inv0, o[ni][1] * inv0);
        g_aoh[r1b + pr] = pack_f16(o[ni][2] * inv1, o[ni][3] * inv1);
    }
}

// ---------------------------------------------------------------------------
extern "C" void kernel_launch(void* const* d_in, const int* in_sizes, int n_in,
                              void* d_out, int out_size) {
    const float* x     = (const float*)d_in[0];
    const float* w_qkv = (const float*)d_in[1];
    const float* w_out = (const float*)d_in[2];
    float* out = (float*)d_out;

    cudaFuncSetAttribute(mm_ldsm<0>, cudaFuncAttributeMaxDynamicSharedMemorySize, MM_SMEM_BYTES);
    cudaFuncSetAttribute(mm_ldsm<1>, cudaFuncAttributeMaxDynamicSharedMemorySize, MM_SMEM_BYTES);
    cudaFuncSetAttribute(flash_mma,  cudaFuncAttributeMaxDynamicSharedMemorySize, FLASH_SMEM_BYTES);

    uint32_t *xh, *wqh, *wql, *woh, *wol, *aoh;
    cudaGetSymbolAddress((void**)&xh,  g_xh);
    cudaGetSymbolAddress((void**)&wqh, g_wqh); cudaGetSymbolAddress((void**)&wql, g_wql);
    cudaGetSymbolAddress((void**)&woh, g_woh); cudaGetSymbolAddress((void**)&wol, g_wol);
    cudaGetSymbolAddress((void**)&aoh, g_aoh);

    // 0) fused pre-pack (single launch)
    prep_all<<<(NPX + NPWQ + NPWO + 255) / 256, 256>>>(x, w_qkv, w_out);

    // 1) QKV projection + fused RoPE
    mm_ldsm<0><<<dim3(24, 64), 256, MM_SMEM_BYTES>>>(xh, wqh, wql, nullptr);

    // 2) V transpose + fp16 pack (2 tiles per block)
    v_convert<<<dim3(S_/128, H_, B_), 128>>>();

    // 3) Flash attention (PV single-pass)
    flash_mma<<<dim3(S_/128, H_, B_), 256, FLASH_SMEM_BYTES>>>();

    // 4) Output projection
    mm_ldsm<1><<<dim3(8, 64), 256, MM_SMEM_BYTES>>>(aoh, woh, wol, out);
}